// round 10
// baseline (speedup 1.0000x reference)
#include <cuda_runtime.h>
#include <cuda_bf16.h>
#include <cstdint>

#define BATCH 2048
#define NCLS  1000
#define CPAD  1024          // centers padded row count
#define DIM   128
#define TM 128
#define TN 64
#define ROWB 272            // bf16 smem row stride: 256B + 16B pad (conflict-free)
#define NCTA 256
#define STW 68              // f32 staging row stride in floats (272B)

// ---- device scratch (allocation-free rule: device globals) ----
__device__ __align__(16) __nv_bfloat16 g_featb[BATCH * DIM];   // 512 KB
__device__ __align__(16) __nv_bfloat16 g_cenb[CPAD * DIM];     // 256 KB
__device__ __align__(16) float g_fn[BATCH];                    // 0.5*||f||^2
__device__ __align__(16) float g_cn[CPAD];                     // 0.5*||c||^2
__device__ int g_is64;
__device__ __align__(16) float g_part[NCTA];
__device__ int g_ticket;

// ---- smem byte offsets (main kernel) ----
#define OFF_A   0                       // A bf16 tile: 128 x 272B = 34816
#define OFF_B   34816                   // B bf16 tile:  64 x 272B = 17408
#define OFF_ST  0                       // f32 dots 128 x 272B = 34816 (aliases A)
#define OFF_RED 52224                   // float[8] warp partials
#define SMEM_BYTES 52288

static __device__ __forceinline__ uint32_t smem_u32(const void* p) {
    uint32_t a;
    asm("{ .reg .u64 t; cvta.to.shared.u64 t, %1; cvt.u32.u64 %0, t; }"
        : "=r"(a) : "l"(p));
    return a;
}

static __device__ __forceinline__ int get_label(const void* lab, int b, int is64) {
    if (is64) return (int)(((const long long*)lab)[b]);
    return ((const int*)lab)[b];
}

static __device__ __forceinline__ uint32_t bf2(float x, float y) {
    __nv_bfloat162 v = __floats2bfloat162_rn(x, y);
    return *(uint32_t*)&v;
}

#define LDSM_X4(d, addr)                                                        \
    asm volatile("ldmatrix.sync.aligned.m8n8.x4.shared.b16 {%0,%1,%2,%3},[%4];" \
        : "=r"((d)[0]), "=r"((d)[1]), "=r"((d)[2]), "=r"((d)[3])                \
        : "r"(addr))

#define MMA16816(d, a, b0, b1)                                                  \
    asm volatile("mma.sync.aligned.m16n8k16.row.col.f32.bf16.bf16.f32 "         \
        "{%0,%1,%2,%3}, {%4,%5,%6,%7}, {%8,%9}, {%0,%1,%2,%3};"                 \
        : "+f"((d)[0]), "+f"((d)[1]), "+f"((d)[2]), "+f"((d)[3])                \
        : "r"((a)[0]), "r"((a)[1]), "r"((a)[2]), "r"((a)[3]),                   \
          "r"(b0), "r"(b1))

// ---------------------------------------------------------------------------
// Prepass: convert feat + centers to bf16 ONCE, compute 0.5*row norms,
// probe label dtype. One warp per row; lane holds one float4.
// ---------------------------------------------------------------------------
__global__ void __launch_bounds__(256)
prepass_kernel(const float* __restrict__ feat,
               const float* __restrict__ centers,
               const void*  __restrict__ label)
{
    // label dtype probe (CTA 0): int64 labels < 1000 => high words all zero
    int hw = 0;
    if (blockIdx.x == 0 && threadIdx.x < 128)
        hw = (((const int*)label)[2 * threadIdx.x + 1] != 0);
    int any = __syncthreads_or(hw);
    if (blockIdx.x == 0 && threadIdx.x == 0) g_is64 = !any;

    const int row  = blockIdx.x * 8 + (threadIdx.x >> 5);
    const int lane = threadIdx.x & 31;

    const float* src;
    __nv_bfloat16* dst;
    float* ndst;
    bool zero = false;
    if (row < BATCH) {
        src = feat + (size_t)row * DIM;
        dst = g_featb + (size_t)row * DIM;
        ndst = g_fn + row;
    } else {
        const int c = row - BATCH;
        zero = (c >= NCLS);
        src = centers + (size_t)c * DIM;
        dst = g_cenb + (size_t)c * DIM;
        ndst = g_cn + c;
    }

    float4 v = zero ? make_float4(0.f, 0.f, 0.f, 0.f)
                    : ((const float4*)src)[lane];
    float s = v.x * v.x + v.y * v.y + v.z * v.z + v.w * v.w;

    uint2 p;
    p.x = bf2(v.x, v.y);
    p.y = bf2(v.z, v.w);
    *(uint2*)(dst + lane * 4) = p;

#pragma unroll
    for (int o = 16; o > 0; o >>= 1) s += __shfl_xor_sync(0xffffffffu, s, o);
    if (lane == 0) *ndst = 0.5f * s;
}

// ---------------------------------------------------------------------------
// Main: 128x64 tile, 8 warps, 2 CTAs/SM for phase overlap.
// ---------------------------------------------------------------------------
__global__ void __launch_bounds__(256, 2)
lgm_mma_kernel(const void* __restrict__ label,
               float* __restrict__ logits,
               float* __restrict__ mlogits,
               float* __restrict__ lik)
{
    extern __shared__ char smem[];
    const uint32_t sb = smem_u32(smem);
    const int tid = threadIdx.x;
    const int bb = blockIdx.y * TM;      // feat-row base
    const int cc = blockIdx.x * TN;      // center-row base

    const int wid  = tid >> 5;
    const int lane = tid & 31;
    const int is64 = g_is64;

    // ------------- staging: copy bf16 tiles straight into smem ---------------
    // A: 32KB, 8 x uint4/thread; B: 16KB, 4 x uint4/thread.
    // chunk j covers 16 rows (256 thr x 16B = 4096B); row = j*16+(tid>>4).
    {
        const char* srcA = (const char*)(g_featb + (size_t)bb * DIM);
        const char* srcB = (const char*)(g_cenb + (size_t)cc * DIM);
        uint4 va[8], vb[4];
#pragma unroll
        for (int j = 0; j < 8; j++) va[j] = *(const uint4*)(srcA + j * 4096 + tid * 16);
#pragma unroll
        for (int j = 0; j < 4; j++) vb[j] = *(const uint4*)(srcB + j * 4096 + tid * 16);
        const uint32_t soff = (tid >> 4) * ROWB + (tid & 15) * 16;
#pragma unroll
        for (int j = 0; j < 8; j++)
            *(uint4*)(smem + OFF_A + j * 16 * ROWB + soff) = va[j];
#pragma unroll
        for (int j = 0; j < 4; j++)
            *(uint4*)(smem + OFF_B + j * 16 * ROWB + soff) = vb[j];
    }

    // preload epilogue operands (latency hides behind barrier + mainloop)
    // warp owns rows [wid*16, wid*16+16); half-warp rh=lane>>4 takes odd/even
    const int rh = lane >> 4;
    int   labs[8];
    float fns[8];
    {
        const int rowbase = bb + wid * 16 + rh;
#pragma unroll
        for (int i = 0; i < 8; i++) {
            labs[i] = get_label(label, rowbase + 2 * i, is64);
            fns[i]  = g_fn[rowbase + 2 * i];
        }
    }
    const float4 cn = *(const float4*)(g_cn + cc + (lane & 15) * 4);

    __syncthreads();

    // ------------- HMMA mainloop: 8 warps, warp = 32(M) x 32(N) --------------
    const int wm = wid & 3;          // rows wm*32..+31
    const int wn = wid >> 2;         // cols wn*32..+31

    const uint32_t la  = sb + OFF_A + (wm * 32 + (lane & 15)) * ROWB + (lane >> 4) * 16;
    const uint32_t lbm = sb + OFF_B + (wn * 32 + (lane & 15)) * ROWB + (lane >> 4) * 16;

    float acc[2][4][4] = {};
    uint32_t a[2][2][4], b[2][2][4];      // [buf][half][frag]
    LDSM_X4(a[0][0], la);
    LDSM_X4(a[0][1], la + 16 * ROWB);
    LDSM_X4(b[0][0], lbm);
    LDSM_X4(b[0][1], lbm + 16 * ROWB);
#pragma unroll
    for (int ks = 0; ks < 8; ks++) {
        const int cur = ks & 1, nxt = cur ^ 1;
        if (ks < 7) {
            const uint32_t ko = (ks + 1) * 32;
            LDSM_X4(a[nxt][0], la + ko);
            LDSM_X4(a[nxt][1], la + 16 * ROWB + ko);
            LDSM_X4(b[nxt][0], lbm + ko);
            LDSM_X4(b[nxt][1], lbm + 16 * ROWB + ko);
        }
#pragma unroll
        for (int mi = 0; mi < 2; mi++)
#pragma unroll
            for (int nb = 0; nb < 2; nb++) {
                MMA16816(acc[mi][nb * 2 + 0], a[cur][mi], b[cur][nb][0], b[cur][nb][2]);
                MMA16816(acc[mi][nb * 2 + 1], a[cur][mi], b[cur][nb][1], b[cur][nb][3]);
            }
    }

    // ------------- stage raw dots into f32 smem tile (aliases A) -------------
    __syncthreads();                       // all ldmatrix reads done
    float* st = (float*)(smem + OFF_ST);
    const int g  = lane >> 2;
    const int tc = lane & 3;
#pragma unroll
    for (int mi = 0; mi < 2; mi++)
#pragma unroll
        for (int nf = 0; nf < 4; nf++)
#pragma unroll
            for (int rr = 0; rr < 2; rr++) {
                const int row = wm * 32 + mi * 16 + g + rr * 8;
                const int col = wn * 32 + nf * 8 + tc * 2;
                *(float2*)&st[row * STW + col] =
                    make_float2(acc[mi][nf][rr * 2], acc[mi][nf][rr * 2 + 1]);
            }
    __syncthreads();

    // ------------- coalesced epilogue: warp owns 16 full rows -----------------
    // iteration i: half-warp rh handles row wid*16 + 2i + rh, cols (lane&15)*4
    const int c = cc + (lane & 15) * 4;
    const bool ok = c < NCLS;

    float lacc = 0.f;
#pragma unroll
    for (int i = 0; i < 8; i++) {
        const int row = wid * 16 + 2 * i + rh;
        const int m = bb + row;
        const float4 d = *(const float4*)&st[row * STW + (lane & 15) * 4];
        const float fn = fns[i];
        const int lb = labs[i];
        float4 lg;
        lg.x = d.x - fn - cn.x;
        lg.y = d.y - fn - cn.y;
        lg.z = d.z - fn - cn.z;
        lg.w = d.w - fn - cn.w;
        float4 ml = lg;
        if (lb == c + 0) { ml.x = 2.f * lg.x; lacc += lg.x; }
        if (lb == c + 1) { ml.y = 2.f * lg.y; lacc += lg.y; }
        if (lb == c + 2) { ml.z = 2.f * lg.z; lacc += lg.z; }
        if (lb == c + 3) { ml.w = 2.f * lg.w; lacc += lg.w; }
        if (ok) {
            const size_t off = (size_t)m * NCLS + c;
            *(float4*)(logits + off)  = lg;
            *(float4*)(mlogits + off) = ml;
        }
    }

    // ------------- likelihood: warp reduce -> CTA partial -> last CTA ---------
#pragma unroll
    for (int o = 16; o > 0; o >>= 1)
        lacc += __shfl_xor_sync(0xffffffffu, lacc, o);
    float* red = (float*)(smem + OFF_RED);
    if (lane == 0) red[wid] = lacc;
    __syncthreads();

    if (tid == 0) {
        float s = ((red[0] + red[1]) + (red[2] + red[3]))
                + ((red[4] + red[5]) + (red[6] + red[7]));
        const int bid = blockIdx.y * 16 + blockIdx.x;
        g_part[bid] = s;
        __threadfence();
        int t = atomicAdd(&g_ticket, 1);
        if (t == NCTA - 1) {
            __threadfence();
            // fixed-order, fixed-split sum => deterministic
            float a0 = 0.f, a1 = 0.f, a2 = 0.f, a3 = 0.f;
            const float4* p4 = (const float4*)g_part;
#pragma unroll
            for (int i = 0; i < NCTA / 4; i++) {
                float4 v = p4[i];
                a0 += v.x; a1 += v.y; a2 += v.z; a3 += v.w;
            }
            *lik = -((a0 + a1) + (a2 + a3)) * (1.f / (float)BATCH);
            g_ticket = 0;          // reset for next graph replay
        }
    }
}

extern "C" void kernel_launch(void* const* d_in, const int* in_sizes, int n_in,
                              void* d_out, int out_size) {
    const float* feat    = (const float*)d_in[0];
    const void*  label   = d_in[1];
    const float* centers = (const float*)d_in[2];

    float* out     = (float*)d_out;
    float* logits  = out;                              // [B, C]
    float* mlogits = out + (size_t)BATCH * NCLS;       // [B, C]
    float* lik     = out + 2 * (size_t)BATCH * NCLS;   // scalar

    cudaFuncSetAttribute(lgm_mma_kernel,
                         cudaFuncAttributeMaxDynamicSharedMemorySize, SMEM_BYTES);

    // convert once: (2048 + 1024) rows / 8 rows per CTA = 384 CTAs
    prepass_kernel<<<(BATCH + CPAD) / 8, 256>>>(feat, centers, label);

    dim3 grid(16, 16);   // 256 CTAs of 128x64, 2 per SM
    lgm_mma_kernel<<<grid, 256, SMEM_BYTES>>>(label, logits, mlogits, lik);
}